// round 8
// baseline (speedup 1.0000x reference)
#include <cuda_runtime.h>
#include <cuda_bf16.h>
#include <mma.h>
#include <cstdint>

using namespace nvcuda;

// ---------------------------------------------------------------------------
// FSRGraphConv round 8: counting-sort aggregation (R6, proven) +
// WMMA bf16 split-precision GEMM (Xhi@Whi + Xhi@Wlo + Xlo@Whi), base-ISA HMMA.
//   out = [h_dst | feat_mean] @ [W1t ; weight@W2^T] + (W_b + bias)
// ---------------------------------------------------------------------------

#define IN_F   128
#define E_F    32
#define FEAT   160
#define OUT_F  128
#define KTOT   288
#define MAX_NODES 50000
#define MAX_EDGES 800000

__device__ __align__(16) float g_acc[(size_t)MAX_NODES * FEAT];   // feat_mean
__device__ int  g_cnt[MAX_NODES];
__device__ int  g_off[MAX_NODES + 1];
__device__ int  g_cur[MAX_NODES];
__device__ int  g_bsum[256];
__device__ __align__(8) int2 g_pairs[MAX_EDGES];
__device__ __align__(16) float g_Wc[FEAT * OUT_F];                // weight @ W2^T
__device__ __align__(16) __nv_bfloat16 g_Bhi[KTOT * OUT_F];       // B[k][n] hi
__device__ __align__(16) __nv_bfloat16 g_Blo[KTOT * OUT_F];       // B[k][n] lo
__device__ __align__(16) float g_bvt[16 * OUT_F];                 // 16 rows of W_b+bias

// ========================= aggregation (unchanged R6) =======================
__global__ void zero_cnt_kernel(int n_nodes) {
    int i = blockIdx.x * blockDim.x + threadIdx.x;
    if (i < n_nodes) g_cnt[i] = 0;
}

__global__ void hist_kernel(const int* __restrict__ dst_idx, int n_edges) {
    int i = blockIdx.x * blockDim.x + threadIdx.x;
    if (i < n_edges) atomicAdd(&g_cnt[dst_idx[i]], 1);
}

__global__ void scanA_kernel(int n) {
    __shared__ int ss[256];
    int b = blockIdx.x, t = threadIdx.x, i = b * 256 + t;
    int c = (i < n) ? g_cnt[i] : 0;
    ss[t] = c; __syncthreads();
    for (int off = 1; off < 256; off <<= 1) {
        int v = (t >= off) ? ss[t - off] : 0;
        __syncthreads();
        ss[t] += v;
        __syncthreads();
    }
    if (i < n) g_off[i] = ss[t] - c;
    if (t == 255) g_bsum[b] = ss[255];
}

__global__ void scanB_kernel(int nb, int n) {
    __shared__ int ss[256];
    int t = threadIdx.x;
    int v = (t < nb) ? g_bsum[t] : 0;
    ss[t] = v; __syncthreads();
    for (int off = 1; off < 256; off <<= 1) {
        int x = (t >= off) ? ss[t - off] : 0;
        __syncthreads();
        ss[t] += x;
        __syncthreads();
    }
    if (t < nb) g_bsum[t] = ss[t] - v;
    if (t == 255) g_off[n] = ss[255];
}

__global__ void scanC_kernel(int n) {
    int i = blockIdx.x * 256 + threadIdx.x;
    if (i < n) {
        int o = g_off[i] + g_bsum[blockIdx.x];
        g_off[i] = o;
        g_cur[i] = o;
    }
}

__global__ void bucket_kernel(const int* __restrict__ src_idx,
                              const int* __restrict__ dst_idx,
                              int n_edges) {
    int e = blockIdx.x * blockDim.x + threadIdx.x;
    if (e < n_edges) {
        int d = dst_idx[e];
        int pos = atomicAdd(&g_cur[d], 1);
        g_pairs[pos] = make_int2(src_idx[e], e);
    }
}

__global__ void aggregate_kernel(const float* __restrict__ h,
                                 const float* __restrict__ eftr,
                                 int n_nodes) {
    int lane = threadIdx.x & 31;
    int w    = (blockIdx.x * blockDim.x + threadIdx.x) >> 5;
    if (w >= n_nodes) return;

    int start = g_off[w];
    int end   = g_off[w + 1];
    int n     = end - start;

    float4 a0 = make_float4(0.f, 0.f, 0.f, 0.f);
    float4 a1 = make_float4(0.f, 0.f, 0.f, 0.f);
    float  e0 = 0.f, e1 = 0.f;

    int j = start;
    for (; j + 1 < end; j += 2) {
        int2 c0 = g_pairs[j];
        int2 c1 = g_pairs[j + 1];
        float4 h0 = __ldg(reinterpret_cast<const float4*>(h + (size_t)c0.x * IN_F) + lane);
        float4 h1 = __ldg(reinterpret_cast<const float4*>(h + (size_t)c1.x * IN_F) + lane);
        float  v0 = __ldg(eftr + (size_t)c0.y * E_F + lane);
        float  v1 = __ldg(eftr + (size_t)c1.y * E_F + lane);
        a0.x += h0.x; a0.y += h0.y; a0.z += h0.z; a0.w += h0.w; e0 += v0;
        a1.x += h1.x; a1.y += h1.y; a1.z += h1.z; a1.w += h1.w; e1 += v1;
    }
    if (j < end) {
        int2 c0 = g_pairs[j];
        float4 h0 = __ldg(reinterpret_cast<const float4*>(h + (size_t)c0.x * IN_F) + lane);
        float  v0 = __ldg(eftr + (size_t)c0.y * E_F + lane);
        a0.x += h0.x; a0.y += h0.y; a0.z += h0.z; a0.w += h0.w; e0 += v0;
    }

    float inv = 1.f / (float)max(n, 1);
    float4 ah = make_float4((a0.x + a1.x) * inv, (a0.y + a1.y) * inv,
                            (a0.z + a1.z) * inv, (a0.w + a1.w) * inv);
    float  ae = (e0 + e1) * inv;

    float* arow = g_acc + (size_t)w * FEAT;
    reinterpret_cast<float4*>(arow)[lane] = ah;
    arow[IN_F + lane] = ae;
}

// ========================= weight prep =====================================
__global__ void prep_wc_kernel(const float* __restrict__ weight,
                               const float* __restrict__ W_w) {
    __shared__ float wrow[OUT_F];
    int k = blockIdx.x;
    int o = threadIdx.x;
    wrow[o] = weight[k * OUT_F + o];
    __syncthreads();
    const float* wr = W_w + (size_t)o * (IN_F + OUT_F) + IN_F;
    float s = 0.f;
#pragma unroll 4
    for (int c = 0; c < OUT_F; c++) s = fmaf(wrow[c], wr[c], s);
    g_Wc[k * OUT_F + o] = s;
}

// B[k][n]: k<128 -> W_w[n][k]; else g_Wc[k-128][n]. Split to bf16 hi/lo.
__global__ void prep_B_kernel(const float* __restrict__ W_w) {
    int k = blockIdx.x;      // 0..287
    int n = threadIdx.x;     // 0..127
    float w = (k < IN_F) ? W_w[(size_t)n * (IN_F + OUT_F) + k]
                         : g_Wc[(size_t)(k - IN_F) * OUT_F + n];
    __nv_bfloat16 hi = __float2bfloat16(w);
    __nv_bfloat16 lo = __float2bfloat16(w - __bfloat162float(hi));
    g_Bhi[(size_t)k * OUT_F + n] = hi;
    g_Blo[(size_t)k * OUT_F + n] = lo;
}

__global__ void prep_bvt_kernel(const float* __restrict__ W_b,
                                const float* __restrict__ bias) {
    int r = blockIdx.x;      // 0..15
    int o = threadIdx.x;
    g_bvt[r * OUT_F + o] = W_b[o] + bias[o];
}

// ========================= WMMA bf16 GEMM ===================================
// BM=128, BN=128, BK=16, 18 chunks. 256 threads = 8 warps (4 M x 2 N),
// warp tile 32(M) x 64(N) = 2x4 m16n16k16 accum frags.
// 3 products per k-chunk: hi*hi + hi*lo + lo*hi.
#define BM 128
#define BN 128
#define BK 16
#define NKC 18

// smem: tiles (16KB) during mainloop; reused as C staging (64KB) in epilogue
#define SM_XHI 0
#define SM_XLO 4096
#define SM_BHI 8192
#define SM_BLO 12288
#define SM_TOTAL 65536

__device__ __forceinline__ uint32_t pk_bf2(__nv_bfloat16 a, __nv_bfloat16 b) {
    return (uint32_t)__bfloat16_as_ushort(a) |
           ((uint32_t)__bfloat16_as_ushort(b) << 16);
}

__global__ __launch_bounds__(256) void gemm_wmma_kernel(
    const float* __restrict__ h,
    float* __restrict__ out, int n_nodes)
{
    extern __shared__ __align__(16) char dsm[];
    __nv_bfloat16* Xhi = reinterpret_cast<__nv_bfloat16*>(dsm + SM_XHI);  // [128][16]
    __nv_bfloat16* Xlo = reinterpret_cast<__nv_bfloat16*>(dsm + SM_XLO);
    __nv_bfloat16* Bhi = reinterpret_cast<__nv_bfloat16*>(dsm + SM_BHI);  // [16][128]
    __nv_bfloat16* Blo = reinterpret_cast<__nv_bfloat16*>(dsm + SM_BLO);
    float* Csm = reinterpret_cast<float*>(dsm);                           // [128][128]

    int m0 = blockIdx.x * BM;
    int t  = threadIdx.x;
    int wid = t >> 5;
    int warpM = wid & 3;          // 0..3 -> M offset 32*warpM
    int warpN = wid >> 2;         // 0..1 -> N offset 64*warpN

    // X loads: idx = t, t+256 -> m = idx>>2, kq = idx&3 (4 floats)
    int m_0 = t >> 2,          kq_0 = t & 3;
    int m_1 = (t + 256) >> 2,  kq_1 = (t + 256) & 3;
    // B loads: idx = t -> kr = t>>4, n8 = t&15 (8 bf16)
    int kr = t >> 4, n8 = t & 15;

    float4 xr0, xr1;
    uint4  bh, bl;
    auto load_tile = [&](int kc) {
        int node0 = m0 + m_0, node1 = m0 + m_1;
        int kg0 = kc * BK + kq_0 * 4;
        int kg1 = kc * BK + kq_1 * 4;
        xr0 = make_float4(0.f, 0.f, 0.f, 0.f);
        xr1 = make_float4(0.f, 0.f, 0.f, 0.f);
        if (node0 < n_nodes)
            xr0 = (kg0 < IN_F)
                ? *reinterpret_cast<const float4*>(h + (size_t)node0 * IN_F + kg0)
                : *reinterpret_cast<const float4*>(g_acc + (size_t)node0 * FEAT + (kg0 - IN_F));
        if (node1 < n_nodes)
            xr1 = (kg1 < IN_F)
                ? *reinterpret_cast<const float4*>(h + (size_t)node1 * IN_F + kg1)
                : *reinterpret_cast<const float4*>(g_acc + (size_t)node1 * FEAT + (kg1 - IN_F));
        size_t gb = (size_t)(kc * BK + kr) * OUT_F + n8 * 8;
        bh = *reinterpret_cast<const uint4*>(g_Bhi + gb);
        bl = *reinterpret_cast<const uint4*>(g_Blo + gb);
    };
    auto store_tile = [&]() {
        // X: split fp32 -> bf16 hi/lo, row-major [m][k], ldm=16
        {
            __nv_bfloat16 h0 = __float2bfloat16(xr0.x);
            __nv_bfloat16 h1 = __float2bfloat16(xr0.y);
            __nv_bfloat16 h2 = __float2bfloat16(xr0.z);
            __nv_bfloat16 h3 = __float2bfloat16(xr0.w);
            __nv_bfloat16 l0 = __float2bfloat16(xr0.x - __bfloat162float(h0));
            __nv_bfloat16 l1 = __float2bfloat16(xr0.y - __bfloat162float(h1));
            __nv_bfloat16 l2 = __float2bfloat16(xr0.z - __bfloat162float(h2));
            __nv_bfloat16 l3 = __float2bfloat16(xr0.w - __bfloat162float(h3));
            int e = m_0 * BK + kq_0 * 4;
            *reinterpret_cast<uint2*>(Xhi + e) = make_uint2(pk_bf2(h0, h1), pk_bf2(h2, h3));
            *reinterpret_cast<uint2*>(Xlo + e) = make_uint2(pk_bf2(l0, l1), pk_bf2(l2, l3));
        }
        {
            __nv_bfloat16 h0 = __float2bfloat16(xr1.x);
            __nv_bfloat16 h1 = __float2bfloat16(xr1.y);
            __nv_bfloat16 h2 = __float2bfloat16(xr1.z);
            __nv_bfloat16 h3 = __float2bfloat16(xr1.w);
            __nv_bfloat16 l0 = __float2bfloat16(xr1.x - __bfloat162float(h0));
            __nv_bfloat16 l1 = __float2bfloat16(xr1.y - __bfloat162float(h1));
            __nv_bfloat16 l2 = __float2bfloat16(xr1.z - __bfloat162float(h2));
            __nv_bfloat16 l3 = __float2bfloat16(xr1.w - __bfloat162float(h3));
            int e = m_1 * BK + kq_1 * 4;
            *reinterpret_cast<uint2*>(Xhi + e) = make_uint2(pk_bf2(h0, h1), pk_bf2(h2, h3));
            *reinterpret_cast<uint2*>(Xlo + e) = make_uint2(pk_bf2(l0, l1), pk_bf2(l2, l3));
        }
        int e = kr * BN + n8 * 8;
        *reinterpret_cast<uint4*>(Bhi + e) = bh;
        *reinterpret_cast<uint4*>(Blo + e) = bl;
    };

    // accumulators init = bias (broadcast rows in g_bvt)
    wmma::fragment<wmma::accumulator, 16, 16, 16, float> c[2][4];
#pragma unroll
    for (int i = 0; i < 2; i++)
#pragma unroll
        for (int j = 0; j < 4; j++)
            wmma::load_matrix_sync(c[i][j], g_bvt + warpN * 64 + j * 16,
                                   OUT_F, wmma::mem_row_major);

    load_tile(0);

    for (int kc = 0; kc < NKC; kc++) {
        store_tile();
        __syncthreads();
        if (kc + 1 < NKC) load_tile(kc + 1);

        wmma::fragment<wmma::matrix_a, 16, 16, 16, __nv_bfloat16, wmma::row_major> ah[2], al[2];
        wmma::fragment<wmma::matrix_b, 16, 16, 16, __nv_bfloat16, wmma::row_major> wh[4], wl[4];
#pragma unroll
        for (int i = 0; i < 2; i++) {
            const __nv_bfloat16* ap = Xhi + (warpM * 32 + i * 16) * BK;
            wmma::load_matrix_sync(ah[i], ap, BK);
            wmma::load_matrix_sync(al[i], Xlo + (warpM * 32 + i * 16) * BK, BK);
        }
#pragma unroll
        for (int j = 0; j < 4; j++) {
            wmma::load_matrix_sync(wh[j], Bhi + warpN * 64 + j * 16, BN);
            wmma::load_matrix_sync(wl[j], Blo + warpN * 64 + j * 16, BN);
        }
#pragma unroll
        for (int i = 0; i < 2; i++)
#pragma unroll
            for (int j = 0; j < 4; j++) {
                wmma::mma_sync(c[i][j], ah[i], wh[j], c[i][j]);
                wmma::mma_sync(c[i][j], ah[i], wl[j], c[i][j]);
                wmma::mma_sync(c[i][j], al[i], wh[j], c[i][j]);
            }
        __syncthreads();
    }

    // epilogue: stage C in smem (reuses tile space), then guarded copy-out
#pragma unroll
    for (int i = 0; i < 2; i++)
#pragma unroll
        for (int j = 0; j < 4; j++)
            wmma::store_matrix_sync(
                Csm + (size_t)(warpM * 32 + i * 16) * BN + warpN * 64 + j * 16,
                c[i][j], BN, wmma::mem_row_major);
    __syncthreads();

#pragma unroll
    for (int p = 0; p < 16; p++) {
        int idx = t + p * 256;       // 0..4095
        int row = idx >> 5;
        int c4  = idx & 31;
        int node = m0 + row;
        if (node < n_nodes) {
            *reinterpret_cast<float4*>(out + (size_t)node * OUT_F + c4 * 4) =
                *reinterpret_cast<const float4*>(Csm + (size_t)row * BN + c4 * 4);
        }
    }
}

// ---------------------------------------------------------------------------
extern "C" void kernel_launch(void* const* d_in, const int* in_sizes, int n_in,
                              void* d_out, int out_size) {
    const float* h      = (const float*)d_in[0];
    const float* eftr   = (const float*)d_in[1];
    const float* weight = (const float*)d_in[2];
    const float* W_w    = (const float*)d_in[3];
    const float* W_b    = (const float*)d_in[4];
    const float* bias   = (const float*)d_in[5];
    const int*   src    = (const int*)d_in[6];
    const int*   dst    = (const int*)d_in[7];
    float* out = (float*)d_out;

    int n_nodes = in_sizes[0] / IN_F;
    int n_edges = in_sizes[7];
    int nb = (n_nodes + 255) / 256;

    static bool attr_done = false;
    if (!attr_done) {
        cudaFuncSetAttribute(gemm_wmma_kernel,
                             cudaFuncAttributeMaxDynamicSharedMemorySize, SM_TOTAL);
        attr_done = true;
    }

    zero_cnt_kernel<<<nb, 256>>>(n_nodes);
    prep_wc_kernel<<<FEAT, OUT_F>>>(weight, W_w);
    prep_B_kernel<<<KTOT, OUT_F>>>(W_w);
    prep_bvt_kernel<<<16, OUT_F>>>(W_b, bias);
    hist_kernel<<<(n_edges + 255) / 256, 256>>>(dst, n_edges);
    scanA_kernel<<<nb, 256>>>(n_nodes);
    scanB_kernel<<<1, 256>>>(nb, n_nodes);
    scanC_kernel<<<nb, 256>>>(n_nodes);
    bucket_kernel<<<(n_edges + 255) / 256, 256>>>(src, dst, n_edges);
    aggregate_kernel<<<(n_nodes * 32 + 255) / 256, 256>>>(h, eftr, n_nodes);
    gemm_wmma_kernel<<<(n_nodes + BM - 1) / BM, 256, SM_TOTAL>>>(h, out, n_nodes);
}

// round 9
// speedup vs baseline: 1.2168x; 1.2168x over previous
#include <cuda_runtime.h>
#include <cuda_bf16.h>
#include <mma.h>
#include <cstdint>

using namespace nvcuda;

// ---------------------------------------------------------------------------
// FSRGraphConv round 9: counting-sort aggregation + pre-split bf16 X (hi/lo) +
// WMMA bf16 split-precision GEMM (Xhi@Bhi + Xhi@Blo + Xlo@Bhi), BK=32,
// conflict-free smem, register-prefetch pipeline.
// ---------------------------------------------------------------------------

#define IN_F   128
#define E_F    32
#define FEAT   160
#define OUT_F  128
#define KTOT   288
#define MAX_NODES 50000
#define NPAD   50048          // 391 * 128
#define MAX_EDGES 800000
#define XLD    288            // X row stride (elements)

__device__ int  g_cnt[MAX_NODES];
__device__ int  g_off[MAX_NODES + 1];
__device__ int  g_cur[MAX_NODES];
__device__ int  g_bsum[256];
__device__ __align__(8) int2 g_pairs[MAX_EDGES];
__device__ __align__(16) float g_Wc[FEAT * OUT_F];
__device__ __align__(16) __nv_bfloat16 g_Xhi[(size_t)NPAD * XLD];
__device__ __align__(16) __nv_bfloat16 g_Xlo[(size_t)NPAD * XLD];
__device__ __align__(16) __nv_bfloat16 g_Bhi[KTOT * OUT_F];   // [k][n]
__device__ __align__(16) __nv_bfloat16 g_Blo[KTOT * OUT_F];
__device__ __align__(16) float g_bvt[16 * OUT_F];

// ========================= sort-based aggregation ===========================
__global__ void zero_cnt_kernel(int n_nodes) {
    int i = blockIdx.x * blockDim.x + threadIdx.x;
    if (i < n_nodes) g_cnt[i] = 0;
}

__global__ void hist_kernel(const int* __restrict__ dst_idx, int n_edges) {
    int i = blockIdx.x * blockDim.x + threadIdx.x;
    if (i < n_edges) atomicAdd(&g_cnt[dst_idx[i]], 1);
}

__global__ void scanA_kernel(int n) {
    __shared__ int ss[256];
    int b = blockIdx.x, t = threadIdx.x, i = b * 256 + t;
    int c = (i < n) ? g_cnt[i] : 0;
    ss[t] = c; __syncthreads();
    for (int off = 1; off < 256; off <<= 1) {
        int v = (t >= off) ? ss[t - off] : 0;
        __syncthreads();
        ss[t] += v;
        __syncthreads();
    }
    if (i < n) g_off[i] = ss[t] - c;
    if (t == 255) g_bsum[b] = ss[255];
}

__global__ void scanB_kernel(int nb, int n) {
    __shared__ int ss[256];
    int t = threadIdx.x;
    int v = (t < nb) ? g_bsum[t] : 0;
    ss[t] = v; __syncthreads();
    for (int off = 1; off < 256; off <<= 1) {
        int x = (t >= off) ? ss[t - off] : 0;
        __syncthreads();
        ss[t] += x;
        __syncthreads();
    }
    if (t < nb) g_bsum[t] = ss[t] - v;
    if (t == 255) g_off[n] = ss[255];
}

__global__ void scanC_kernel(int n) {
    int i = blockIdx.x * 256 + threadIdx.x;
    if (i < n) {
        int o = g_off[i] + g_bsum[blockIdx.x];
        g_off[i] = o;
        g_cur[i] = o;
    }
}

__global__ void bucket_kernel(const int* __restrict__ src_idx,
                              const int* __restrict__ dst_idx,
                              int n_edges) {
    int e = blockIdx.x * blockDim.x + threadIdx.x;
    if (e < n_edges) {
        int d = dst_idx[e];
        int pos = atomicAdd(&g_cur[d], 1);
        g_pairs[pos] = make_int2(src_idx[e], e);
    }
}

__device__ __forceinline__ uint32_t pk_bf2(__nv_bfloat16 a, __nv_bfloat16 b) {
    return (uint32_t)__bfloat16_as_ushort(a) |
           ((uint32_t)__bfloat16_as_ushort(b) << 16);
}
__device__ __forceinline__ void split4(float4 v, uint2& hi, uint2& lo) {
    __nv_bfloat16 h0 = __float2bfloat16(v.x);
    __nv_bfloat16 h1 = __float2bfloat16(v.y);
    __nv_bfloat16 h2 = __float2bfloat16(v.z);
    __nv_bfloat16 h3 = __float2bfloat16(v.w);
    __nv_bfloat16 l0 = __float2bfloat16(v.x - __bfloat162float(h0));
    __nv_bfloat16 l1 = __float2bfloat16(v.y - __bfloat162float(h1));
    __nv_bfloat16 l2 = __float2bfloat16(v.z - __bfloat162float(h2));
    __nv_bfloat16 l3 = __float2bfloat16(v.w - __bfloat162float(h3));
    hi = make_uint2(pk_bf2(h0, h1), pk_bf2(h2, h3));
    lo = make_uint2(pk_bf2(l0, l1), pk_bf2(l2, l3));
}

// convert h rows into X cols [0,128): thread = (node, lane covering 4 cols)
__global__ void hconv_kernel(const float* __restrict__ h, int n_nodes) {
    int gid  = blockIdx.x * blockDim.x + threadIdx.x;
    int node = gid >> 5;
    int lane = gid & 31;
    if (node >= n_nodes) return;
    float4 v = __ldg(reinterpret_cast<const float4*>(h + (size_t)node * IN_F) + lane);
    uint2 hi, lo;
    split4(v, hi, lo);
    size_t e = (size_t)node * XLD + lane * 4;
    *reinterpret_cast<uint2*>(g_Xhi + e) = hi;
    *reinterpret_cast<uint2*>(g_Xlo + e) = lo;
}

// warp per dst: mean over sorted edges, write X cols [128,288) as bf16 hi/lo
__global__ void aggregate_kernel(const float* __restrict__ h,
                                 const float* __restrict__ eftr,
                                 int n_nodes) {
    int lane = threadIdx.x & 31;
    int w    = (blockIdx.x * blockDim.x + threadIdx.x) >> 5;
    if (w >= n_nodes) return;

    int start = g_off[w];
    int end   = g_off[w + 1];
    int n     = end - start;

    float4 a0 = make_float4(0.f, 0.f, 0.f, 0.f);
    float4 a1 = make_float4(0.f, 0.f, 0.f, 0.f);
    float  e0 = 0.f, e1 = 0.f;

    int j = start;
    for (; j + 1 < end; j += 2) {
        int2 c0 = g_pairs[j];
        int2 c1 = g_pairs[j + 1];
        float4 h0 = __ldg(reinterpret_cast<const float4*>(h + (size_t)c0.x * IN_F) + lane);
        float4 h1 = __ldg(reinterpret_cast<const float4*>(h + (size_t)c1.x * IN_F) + lane);
        float  v0 = __ldg(eftr + (size_t)c0.y * E_F + lane);
        float  v1 = __ldg(eftr + (size_t)c1.y * E_F + lane);
        a0.x += h0.x; a0.y += h0.y; a0.z += h0.z; a0.w += h0.w; e0 += v0;
        a1.x += h1.x; a1.y += h1.y; a1.z += h1.z; a1.w += h1.w; e1 += v1;
    }
    if (j < end) {
        int2 c0 = g_pairs[j];
        float4 h0 = __ldg(reinterpret_cast<const float4*>(h + (size_t)c0.x * IN_F) + lane);
        float  v0 = __ldg(eftr + (size_t)c0.y * E_F + lane);
        a0.x += h0.x; a0.y += h0.y; a0.z += h0.z; a0.w += h0.w; e0 += v0;
    }

    float inv = 1.f / (float)max(n, 1);
    float4 ah = make_float4((a0.x + a1.x) * inv, (a0.y + a1.y) * inv,
                            (a0.z + a1.z) * inv, (a0.w + a1.w) * inv);
    float  ae = (e0 + e1) * inv;

    uint2 hi, lo;
    split4(ah, hi, lo);
    size_t eh = (size_t)w * XLD + IN_F + lane * 4;
    *reinterpret_cast<uint2*>(g_Xhi + eh) = hi;
    *reinterpret_cast<uint2*>(g_Xlo + eh) = lo;

    __nv_bfloat16 ehi = __float2bfloat16(ae);
    __nv_bfloat16 elo = __float2bfloat16(ae - __bfloat162float(ehi));
    size_t ee = (size_t)w * XLD + 256 + lane;
    g_Xhi[ee] = ehi;
    g_Xlo[ee] = elo;
}

// ========================= weight prep =====================================
__global__ void prep_wc_kernel(const float* __restrict__ weight,
                               const float* __restrict__ W_w) {
    __shared__ float wrow[OUT_F];
    int k = blockIdx.x;
    int o = threadIdx.x;
    wrow[o] = weight[k * OUT_F + o];
    __syncthreads();
    const float* wr = W_w + (size_t)o * (IN_F + OUT_F) + IN_F;
    float s = 0.f;
#pragma unroll 4
    for (int c = 0; c < OUT_F; c++) s = fmaf(wrow[c], wr[c], s);
    g_Wc[k * OUT_F + o] = s;
}

__global__ void prep_B_kernel(const float* __restrict__ W_w) {
    int k = blockIdx.x;      // 0..287
    int n = threadIdx.x;     // 0..127
    float w = (k < IN_F) ? W_w[(size_t)n * (IN_F + OUT_F) + k]
                         : g_Wc[(size_t)(k - IN_F) * OUT_F + n];
    __nv_bfloat16 hi = __float2bfloat16(w);
    __nv_bfloat16 lo = __float2bfloat16(w - __bfloat162float(hi));
    g_Bhi[(size_t)k * OUT_F + n] = hi;
    g_Blo[(size_t)k * OUT_F + n] = lo;
}

__global__ void prep_bvt_kernel(const float* __restrict__ W_b,
                                const float* __restrict__ bias) {
    int r = blockIdx.x;
    int o = threadIdx.x;
    g_bvt[r * OUT_F + o] = W_b[o] + bias[o];
}

// ========================= WMMA bf16 GEMM ===================================
// BM=128, BN=128, BK=32, 9 chunks. 8 warps (4M x 2N), warp tile 32x64.
// A smem ldm=56 (112B stride, conflict-free), B smem ldm=136 (272B).
#define BM 128
#define BN 128
#define BK 32
#define NKC 9
#define ALDM 56
#define BLDM 136

#define SA_HI 0
#define SA_LO 14336
#define SB_HI 28672
#define SB_LO 37376
#define SM_TOTAL 65536        // C staging (128*128*4) reuses tile space

__global__ __launch_bounds__(256) void gemm_wmma_kernel(
    float* __restrict__ out, int n_nodes)
{
    extern __shared__ __align__(16) char dsm[];
    __nv_bfloat16* Ahi = reinterpret_cast<__nv_bfloat16*>(dsm + SA_HI);
    __nv_bfloat16* Alo = reinterpret_cast<__nv_bfloat16*>(dsm + SA_LO);
    __nv_bfloat16* Bhi = reinterpret_cast<__nv_bfloat16*>(dsm + SB_HI);
    __nv_bfloat16* Blo = reinterpret_cast<__nv_bfloat16*>(dsm + SB_LO);
    float* Csm = reinterpret_cast<float*>(dsm);

    int m0 = blockIdx.x * BM;
    int t  = threadIdx.x;
    int wid = t >> 5;
    int warpM = wid & 3;
    int warpN = wid >> 2;

    // A loads: 128 rows x 32 cols / 8 per unit = 512 units, 2 per thread
    int am0 = t >> 2,          aq0 = t & 3;
    int am1 = (t + 256) >> 2,  aq1 = (t + 256) & 3;
    // B loads: 32 rows x 128 cols / 8 per unit = 512 units, 2 per thread
    int bk0 = t >> 4,          bq0 = t & 15;
    int bk1 = (t + 256) >> 4,  bq1 = (t + 256) & 15;

    uint4 axh[2], axl[2], abh[2], abl[2];
    auto load_tile = [&](int kc) {
        int n0 = m0 + am0, n1 = m0 + am1;
        size_t e0 = (size_t)n0 * XLD + kc * BK + aq0 * 8;
        size_t e1 = (size_t)n1 * XLD + kc * BK + aq1 * 8;
        uint4 z = make_uint4(0u, 0u, 0u, 0u);
        axh[0] = (n0 < n_nodes) ? *reinterpret_cast<const uint4*>(g_Xhi + e0) : z;
        axl[0] = (n0 < n_nodes) ? *reinterpret_cast<const uint4*>(g_Xlo + e0) : z;
        axh[1] = (n1 < n_nodes) ? *reinterpret_cast<const uint4*>(g_Xhi + e1) : z;
        axl[1] = (n1 < n_nodes) ? *reinterpret_cast<const uint4*>(g_Xlo + e1) : z;
        size_t b0 = (size_t)(kc * BK + bk0) * OUT_F + bq0 * 8;
        size_t b1 = (size_t)(kc * BK + bk1) * OUT_F + bq1 * 8;
        abh[0] = *reinterpret_cast<const uint4*>(g_Bhi + b0);
        abl[0] = *reinterpret_cast<const uint4*>(g_Blo + b0);
        abh[1] = *reinterpret_cast<const uint4*>(g_Bhi + b1);
        abl[1] = *reinterpret_cast<const uint4*>(g_Blo + b1);
    };
    auto store_tile = [&]() {
        *reinterpret_cast<uint4*>(Ahi + am0 * ALDM + aq0 * 8) = axh[0];
        *reinterpret_cast<uint4*>(Alo + am0 * ALDM + aq0 * 8) = axl[0];
        *reinterpret_cast<uint4*>(Ahi + am1 * ALDM + aq1 * 8) = axh[1];
        *reinterpret_cast<uint4*>(Alo + am1 * ALDM + aq1 * 8) = axl[1];
        *reinterpret_cast<uint4*>(Bhi + bk0 * BLDM + bq0 * 8) = abh[0];
        *reinterpret_cast<uint4*>(Blo + bk0 * BLDM + bq0 * 8) = abl[0];
        *reinterpret_cast<uint4*>(Bhi + bk1 * BLDM + bq1 * 8) = abh[1];
        *reinterpret_cast<uint4*>(Blo + bk1 * BLDM + bq1 * 8) = abl[1];
    };

    wmma::fragment<wmma::accumulator, 16, 16, 16, float> c[2][4];
#pragma unroll
    for (int i = 0; i < 2; i++)
#pragma unroll
        for (int j = 0; j < 4; j++)
            wmma::load_matrix_sync(c[i][j], g_bvt + warpN * 64 + j * 16,
                                   OUT_F, wmma::mem_row_major);

    load_tile(0);

    for (int kc = 0; kc < NKC; kc++) {
        store_tile();
        __syncthreads();
        if (kc + 1 < NKC) load_tile(kc + 1);

#pragma unroll
        for (int ks = 0; ks < 2; ks++) {
            wmma::fragment<wmma::matrix_a, 16, 16, 16, __nv_bfloat16, wmma::row_major> ah[2], al[2];
            wmma::fragment<wmma::matrix_b, 16, 16, 16, __nv_bfloat16, wmma::row_major> wh[4], wl[4];
#pragma unroll
            for (int i = 0; i < 2; i++) {
                const __nv_bfloat16* ap = Ahi + (warpM * 32 + i * 16) * ALDM + ks * 16;
                const __nv_bfloat16* lp = Alo + (warpM * 32 + i * 16) * ALDM + ks * 16;
                wmma::load_matrix_sync(ah[i], ap, ALDM);
                wmma::load_matrix_sync(al[i], lp, ALDM);
            }
#pragma unroll
            for (int j = 0; j < 4; j++) {
                const __nv_bfloat16* bp = Bhi + (ks * 16) * BLDM + warpN * 64 + j * 16;
                const __nv_bfloat16* lp = Blo + (ks * 16) * BLDM + warpN * 64 + j * 16;
                wmma::load_matrix_sync(wh[j], bp, BLDM);
                wmma::load_matrix_sync(wl[j], lp, BLDM);
            }
#pragma unroll
            for (int i = 0; i < 2; i++)
#pragma unroll
                for (int j = 0; j < 4; j++) {
                    wmma::mma_sync(c[i][j], ah[i], wh[j], c[i][j]);
                    wmma::mma_sync(c[i][j], ah[i], wl[j], c[i][j]);
                    wmma::mma_sync(c[i][j], al[i], wh[j], c[i][j]);
                }
        }
        __syncthreads();
    }

    // epilogue via smem staging
#pragma unroll
    for (int i = 0; i < 2; i++)
#pragma unroll
        for (int j = 0; j < 4; j++)
            wmma::store_matrix_sync(
                Csm + (size_t)(warpM * 32 + i * 16) * BN + warpN * 64 + j * 16,
                c[i][j], BN, wmma::mem_row_major);
    __syncthreads();

#pragma unroll
    for (int p = 0; p < 16; p++) {
        int idx = t + p * 256;
        int row = idx >> 5;
        int c4  = idx & 31;
        int node = m0 + row;
        if (node < n_nodes) {
            *reinterpret_cast<float4*>(out + (size_t)node * OUT_F + c4 * 4) =
                *reinterpret_cast<const float4*>(Csm + (size_t)row * BN + c4 * 4);
        }
    }
}

// ---------------------------------------------------------------------------
extern "C" void kernel_launch(void* const* d_in, const int* in_sizes, int n_in,
                              void* d_out, int out_size) {
    const float* h      = (const float*)d_in[0];
    const float* eftr   = (const float*)d_in[1];
    const float* weight = (const float*)d_in[2];
    const float* W_w    = (const float*)d_in[3];
    const float* W_b    = (const float*)d_in[4];
    const float* bias   = (const float*)d_in[5];
    const int*   src    = (const int*)d_in[6];
    const int*   dst    = (const int*)d_in[7];
    float* out = (float*)d_out;

    int n_nodes = in_sizes[0] / IN_F;
    int n_edges = in_sizes[7];
    int nb = (n_nodes + 255) / 256;

    static bool attr_done = false;
    if (!attr_done) {
        cudaFuncSetAttribute(gemm_wmma_kernel,
                             cudaFuncAttributeMaxDynamicSharedMemorySize, SM_TOTAL);
        attr_done = true;
    }

    zero_cnt_kernel<<<nb, 256>>>(n_nodes);
    prep_wc_kernel<<<FEAT, OUT_F>>>(weight, W_w);
    prep_B_kernel<<<KTOT, OUT_F>>>(W_w);
    prep_bvt_kernel<<<16, OUT_F>>>(W_b, bias);
    hconv_kernel<<<(n_nodes * 32 + 255) / 256, 256>>>(h, n_nodes);
    hist_kernel<<<(n_edges + 255) / 256, 256>>>(dst, n_edges);
    scanA_kernel<<<nb, 256>>>(n_nodes);
    scanB_kernel<<<1, 256>>>(nb, n_nodes);
    scanC_kernel<<<nb, 256>>>(n_nodes);
    bucket_kernel<<<(n_edges + 255) / 256, 256>>>(src, dst, n_edges);
    aggregate_kernel<<<(n_nodes * 32 + 255) / 256, 256>>>(h, eftr, n_nodes);
    gemm_wmma_kernel<<<(n_nodes + BM - 1) / BM, 256, SM_TOTAL>>>(out, n_nodes);
}

// round 10
// speedup vs baseline: 1.3194x; 1.0843x over previous
#include <cuda_runtime.h>
#include <cuda_bf16.h>
#include <mma.h>
#include <cstdint>

using namespace nvcuda;

// ---------------------------------------------------------------------------
// FSRGraphConv round 10: counting-sort aggregation + pre-split bf16 X (hi/lo) +
// cp.async double-buffered WMMA bf16 split-precision GEMM. Merged small kernels.
// ---------------------------------------------------------------------------

#define IN_F   128
#define E_F    32
#define FEAT   160
#define OUT_F  128
#define KTOT   288
#define MAX_NODES 50000
#define NPAD   50048          // 391 * 128 (rows >= n_nodes stay zero forever)
#define MAX_EDGES 800000
#define XLD    288

__device__ int  g_cnt[MAX_NODES];
__device__ int  g_off[MAX_NODES + 1];
__device__ int  g_cur[MAX_NODES];
__device__ int  g_bsum[256];
__device__ __align__(8) int2 g_pairs[MAX_EDGES];
__device__ __align__(16) float g_Wc[FEAT * OUT_F];
__device__ __align__(16) __nv_bfloat16 g_Xhi[(size_t)NPAD * XLD];
__device__ __align__(16) __nv_bfloat16 g_Xlo[(size_t)NPAD * XLD];
__device__ __align__(16) __nv_bfloat16 g_Bhi[KTOT * OUT_F];
__device__ __align__(16) __nv_bfloat16 g_Blo[KTOT * OUT_F];
__device__ __align__(16) float g_bvt[16 * OUT_F];

// ========================= bf16 split helpers ===============================
__device__ __forceinline__ uint32_t pk_bf2(__nv_bfloat16 a, __nv_bfloat16 b) {
    return (uint32_t)__bfloat16_as_ushort(a) |
           ((uint32_t)__bfloat16_as_ushort(b) << 16);
}
__device__ __forceinline__ void split4(float4 v, uint2& hi, uint2& lo) {
    __nv_bfloat16 h0 = __float2bfloat16(v.x);
    __nv_bfloat16 h1 = __float2bfloat16(v.y);
    __nv_bfloat16 h2 = __float2bfloat16(v.z);
    __nv_bfloat16 h3 = __float2bfloat16(v.w);
    __nv_bfloat16 l0 = __float2bfloat16(v.x - __bfloat162float(h0));
    __nv_bfloat16 l1 = __float2bfloat16(v.y - __bfloat162float(h1));
    __nv_bfloat16 l2 = __float2bfloat16(v.z - __bfloat162float(h2));
    __nv_bfloat16 l3 = __float2bfloat16(v.w - __bfloat162float(h3));
    hi = make_uint2(pk_bf2(h0, h1), pk_bf2(h2, h3));
    lo = make_uint2(pk_bf2(l0, l1), pk_bf2(l2, l3));
}

// ===================== merged prep 1: Wc + zero cnt =========================
// blocks [0,160): g_Wc row; blocks [160,...): zero g_cnt. 128 threads.
__global__ void prep1_kernel(const float* __restrict__ weight,
                             const float* __restrict__ W_w, int n_nodes) {
    int b = blockIdx.x;
    if (b < FEAT) {
        __shared__ float wrow[OUT_F];
        int k = b, o = threadIdx.x;
        wrow[o] = weight[k * OUT_F + o];
        __syncthreads();
        const float* wr = W_w + (size_t)o * (IN_F + OUT_F) + IN_F;
        float s = 0.f;
#pragma unroll 4
        for (int c = 0; c < OUT_F; c++) s = fmaf(wrow[c], wr[c], s);
        g_Wc[k * OUT_F + o] = s;
    } else {
        int i = (b - FEAT) * 128 + threadIdx.x;
        if (i < n_nodes) g_cnt[i] = 0;
    }
}

// ===================== prep 2: B hi/lo + bvt =================================
__global__ void prep_B_kernel(const float* __restrict__ W_w,
                              const float* __restrict__ W_b,
                              const float* __restrict__ bias) {
    int k = blockIdx.x;      // 0..287
    int n = threadIdx.x;     // 0..127
    float w = (k < IN_F) ? W_w[(size_t)n * (IN_F + OUT_F) + k]
                         : g_Wc[(size_t)(k - IN_F) * OUT_F + n];
    __nv_bfloat16 hi = __float2bfloat16(w);
    __nv_bfloat16 lo = __float2bfloat16(w - __bfloat162float(hi));
    g_Bhi[(size_t)k * OUT_F + n] = hi;
    g_Blo[(size_t)k * OUT_F + n] = lo;
    if (k < 16) g_bvt[k * OUT_F + n] = W_b[n] + bias[n];
}

// ===================== merged hist + hconv ==================================
// blocks [0,nbh): histogram of dst; blocks [nbh,...): convert h -> Xhi/Xlo[:,0:128]
__global__ void hist_hconv_kernel(const int* __restrict__ dst_idx,
                                  const float* __restrict__ h,
                                  int n_edges, int n_nodes, int nbh) {
    int b = blockIdx.x;
    if (b < nbh) {
        int i = b * 256 + threadIdx.x;
        if (i < n_edges) atomicAdd(&g_cnt[dst_idx[i]], 1);
    } else {
        int gid  = (b - nbh) * 256 + threadIdx.x;
        int node = gid >> 5;
        int lane = gid & 31;
        if (node < n_nodes) {
            float4 v = __ldg(reinterpret_cast<const float4*>(h + (size_t)node * IN_F) + lane);
            uint2 hi, lo;
            split4(v, hi, lo);
            size_t e = (size_t)node * XLD + lane * 4;
            *reinterpret_cast<uint2*>(g_Xhi + e) = hi;
            *reinterpret_cast<uint2*>(g_Xlo + e) = lo;
        }
    }
}

// ===================== 3-kernel coalesced scan ==============================
__global__ void scanA_kernel(int n) {
    __shared__ int ss[256];
    int b = blockIdx.x, t = threadIdx.x, i = b * 256 + t;
    int c = (i < n) ? g_cnt[i] : 0;
    ss[t] = c; __syncthreads();
    for (int off = 1; off < 256; off <<= 1) {
        int v = (t >= off) ? ss[t - off] : 0;
        __syncthreads();
        ss[t] += v;
        __syncthreads();
    }
    if (i < n) g_off[i] = ss[t] - c;
    if (t == 255) g_bsum[b] = ss[255];
}

__global__ void scanB_kernel(int nb, int n) {
    __shared__ int ss[256];
    int t = threadIdx.x;
    int v = (t < nb) ? g_bsum[t] : 0;
    ss[t] = v; __syncthreads();
    for (int off = 1; off < 256; off <<= 1) {
        int x = (t >= off) ? ss[t - off] : 0;
        __syncthreads();
        ss[t] += x;
        __syncthreads();
    }
    if (t < nb) g_bsum[t] = ss[t] - v;
    if (t == 255) g_off[n] = ss[255];
}

__global__ void scanC_kernel(int n) {
    int i = blockIdx.x * 256 + threadIdx.x;
    if (i < n) {
        int o = g_off[i] + g_bsum[blockIdx.x];
        g_off[i] = o;
        g_cur[i] = o;
    }
}

__global__ void bucket_kernel(const int* __restrict__ src_idx,
                              const int* __restrict__ dst_idx,
                              int n_edges) {
    int e = blockIdx.x * blockDim.x + threadIdx.x;
    if (e < n_edges) {
        int d = dst_idx[e];
        int pos = atomicAdd(&g_cur[d], 1);
        g_pairs[pos] = make_int2(src_idx[e], e);
    }
}

// warp per dst: mean over sorted edges -> Xhi/Xlo[:,128:288]
__global__ void aggregate_kernel(const float* __restrict__ h,
                                 const float* __restrict__ eftr,
                                 int n_nodes) {
    int lane = threadIdx.x & 31;
    int w    = (blockIdx.x * blockDim.x + threadIdx.x) >> 5;
    if (w >= n_nodes) return;

    int start = g_off[w];
    int end   = g_off[w + 1];
    int n     = end - start;

    float4 a0 = make_float4(0.f, 0.f, 0.f, 0.f);
    float4 a1 = make_float4(0.f, 0.f, 0.f, 0.f);
    float  e0 = 0.f, e1 = 0.f;

    int j = start;
    for (; j + 1 < end; j += 2) {
        int2 c0 = g_pairs[j];
        int2 c1 = g_pairs[j + 1];
        float4 h0 = __ldg(reinterpret_cast<const float4*>(h + (size_t)c0.x * IN_F) + lane);
        float4 h1 = __ldg(reinterpret_cast<const float4*>(h + (size_t)c1.x * IN_F) + lane);
        float  v0 = __ldg(eftr + (size_t)c0.y * E_F + lane);
        float  v1 = __ldg(eftr + (size_t)c1.y * E_F + lane);
        a0.x += h0.x; a0.y += h0.y; a0.z += h0.z; a0.w += h0.w; e0 += v0;
        a1.x += h1.x; a1.y += h1.y; a1.z += h1.z; a1.w += h1.w; e1 += v1;
    }
    if (j < end) {
        int2 c0 = g_pairs[j];
        float4 h0 = __ldg(reinterpret_cast<const float4*>(h + (size_t)c0.x * IN_F) + lane);
        float  v0 = __ldg(eftr + (size_t)c0.y * E_F + lane);
        a0.x += h0.x; a0.y += h0.y; a0.z += h0.z; a0.w += h0.w; e0 += v0;
    }

    float inv = 1.f / (float)max(n, 1);
    float4 ah = make_float4((a0.x + a1.x) * inv, (a0.y + a1.y) * inv,
                            (a0.z + a1.z) * inv, (a0.w + a1.w) * inv);
    float  ae = (e0 + e1) * inv;

    uint2 hi, lo;
    split4(ah, hi, lo);
    size_t eh = (size_t)w * XLD + IN_F + lane * 4;
    *reinterpret_cast<uint2*>(g_Xhi + eh) = hi;
    *reinterpret_cast<uint2*>(g_Xlo + eh) = lo;

    __nv_bfloat16 ehi = __float2bfloat16(ae);
    __nv_bfloat16 elo = __float2bfloat16(ae - __bfloat162float(ehi));
    size_t ee = (size_t)w * XLD + 256 + lane;
    g_Xhi[ee] = ehi;
    g_Xlo[ee] = elo;
}

// ========================= cp.async WMMA GEMM ===============================
// BM=128, BN=128, BK=32, 9 chunks, 2-stage cp.async double buffer.
// 8 warps (4M x 2N), warp tile 32x64. Loads UNGUARDED (NPAD rows valid+zero).
#define BM 128
#define BN 128
#define BK 32
#define NKC 9
#define ALDM 56              // A smem row stride (bf16), 112B: conflict-free
#define BLDM 136             // B smem row stride, 272B: conflict-free
#define A_BYTES (BM * ALDM * 2)            // 14336
#define B_BYTES (BK * BLDM * 2)            // 8704
#define ST_AHI 0
#define ST_ALO (A_BYTES)
#define ST_BHI (2 * A_BYTES)
#define ST_BLO (2 * A_BYTES + B_BYTES)
#define STAGE_BYTES (2 * A_BYTES + 2 * B_BYTES)   // 46080
#define SM_TOTAL (2 * STAGE_BYTES)                // 92160 (>= 64KB C staging)

__device__ __forceinline__ uint32_t smem_u32(const void* p) {
    return (uint32_t)__cvta_generic_to_shared(p);
}
__device__ __forceinline__ void cp16(uint32_t sdst, const void* gsrc) {
    asm volatile("cp.async.ca.shared.global [%0], [%1], 16;"
                 :: "r"(sdst), "l"(gsrc));
}

__global__ __launch_bounds__(256) void gemm_wmma_kernel(
    float* __restrict__ out, int n_nodes)
{
    extern __shared__ __align__(16) char dsm[];
    float* Csm = reinterpret_cast<float*>(dsm);
    const uint32_t sb = smem_u32(dsm);

    int m0 = blockIdx.x * BM;
    int t  = threadIdx.x;
    int wid = t >> 5;
    int warpM = wid & 3;
    int warpN = wid >> 2;

    // A: 512 16B-units (128 rows x 4), this thread: u=t, t+256
    int am0 = t >> 2,          aq0 = t & 3;
    int am1 = (t + 256) >> 2,  aq1 = (t + 256) & 3;
    // B: 512 16B-units (32 rows x 16)
    int bk0 = t >> 4,          bq0 = t & 15;
    int bk1 = (t + 256) >> 4,  bq1 = (t + 256) & 15;

    const __nv_bfloat16* gA0h = g_Xhi + (size_t)(m0 + am0) * XLD + aq0 * 8;
    const __nv_bfloat16* gA0l = g_Xlo + (size_t)(m0 + am0) * XLD + aq0 * 8;
    const __nv_bfloat16* gA1h = g_Xhi + (size_t)(m0 + am1) * XLD + aq1 * 8;
    const __nv_bfloat16* gA1l = g_Xlo + (size_t)(m0 + am1) * XLD + aq1 * 8;
    const __nv_bfloat16* gB0h = g_Bhi + (size_t)bk0 * OUT_F + bq0 * 8;
    const __nv_bfloat16* gB0l = g_Blo + (size_t)bk0 * OUT_F + bq0 * 8;
    const __nv_bfloat16* gB1h = g_Bhi + (size_t)bk1 * OUT_F + bq1 * 8;
    const __nv_bfloat16* gB1l = g_Blo + (size_t)bk1 * OUT_F + bq1 * 8;

    uint32_t sA0 = sb + (am0 * ALDM + aq0 * 8) * 2;
    uint32_t sA1 = sb + (am1 * ALDM + aq1 * 8) * 2;
    uint32_t sB0 = sb + ST_BHI + (bk0 * BLDM + bq0 * 8) * 2;
    uint32_t sB1 = sb + ST_BHI + (bk1 * BLDM + bq1 * 8) * 2;

    auto load_stage = [&](int kc, int buf) {
        uint32_t so = buf * STAGE_BYTES;
        int ko = kc * BK;
        cp16(sA0 + so,          gA0h + ko);
        cp16(sA0 + so + A_BYTES, gA0l + ko);
        cp16(sA1 + so,          gA1h + ko);
        cp16(sA1 + so + A_BYTES, gA1l + ko);
        size_t bo = (size_t)ko * OUT_F;
        cp16(sB0 + so,          gB0h + bo);
        cp16(sB0 + so + B_BYTES, gB0l + bo);
        cp16(sB1 + so,          gB1h + bo);
        cp16(sB1 + so + B_BYTES, gB1l + bo);
        asm volatile("cp.async.commit_group;");
    };

    wmma::fragment<wmma::accumulator, 16, 16, 16, float> c[2][4];
#pragma unroll
    for (int i = 0; i < 2; i++)
#pragma unroll
        for (int j = 0; j < 4; j++)
            wmma::load_matrix_sync(c[i][j], g_bvt + warpN * 64 + j * 16,
                                   OUT_F, wmma::mem_row_major);

    load_stage(0, 0);

    for (int kc = 0; kc < NKC; kc++) {
        if (kc + 1 < NKC) {
            load_stage(kc + 1, (kc + 1) & 1);
            asm volatile("cp.async.wait_group 1;");
        } else {
            asm volatile("cp.async.wait_group 0;");
        }
        __syncthreads();

        char* st = dsm + (kc & 1) * STAGE_BYTES;
        __nv_bfloat16* Ahi = reinterpret_cast<__nv_bfloat16*>(st);
        __nv_bfloat16* Alo = reinterpret_cast<__nv_bfloat16*>(st + ST_ALO);
        __nv_bfloat16* Bhi = reinterpret_cast<__nv_bfloat16*>(st + ST_BHI);
        __nv_bfloat16* Blo = reinterpret_cast<__nv_bfloat16*>(st + ST_BLO);

#pragma unroll
        for (int ks = 0; ks < 2; ks++) {
            wmma::fragment<wmma::matrix_a, 16, 16, 16, __nv_bfloat16, wmma::row_major> ah[2], al[2];
            wmma::fragment<wmma::matrix_b, 16, 16, 16, __nv_bfloat16, wmma::row_major> wh[4], wl[4];
#pragma unroll
            for (int i = 0; i < 2; i++) {
                wmma::load_matrix_sync(ah[i], Ahi + (warpM * 32 + i * 16) * ALDM + ks * 16, ALDM);
                wmma::load_matrix_sync(al[i], Alo + (warpM * 32 + i * 16) * ALDM + ks * 16, ALDM);
            }
#pragma unroll
            for (int j = 0; j < 4; j++) {
                wmma::load_matrix_sync(wh[j], Bhi + (ks * 16) * BLDM + warpN * 64 + j * 16, BLDM);
                wmma::load_matrix_sync(wl[j], Blo + (ks * 16) * BLDM + warpN * 64 + j * 16, BLDM);
            }
#pragma unroll
            for (int i = 0; i < 2; i++)
#pragma unroll
                for (int j = 0; j < 4; j++) {
                    wmma::mma_sync(c[i][j], ah[i], wh[j], c[i][j]);
                    wmma::mma_sync(c[i][j], ah[i], wl[j], c[i][j]);
                    wmma::mma_sync(c[i][j], al[i], wh[j], c[i][j]);
                }
        }
        __syncthreads();
    }

    // epilogue via smem staging (reuses stage memory)
#pragma unroll
    for (int i = 0; i < 2; i++)
#pragma unroll
        for (int j = 0; j < 4; j++)
            wmma::store_matrix_sync(
                Csm + (size_t)(warpM * 32 + i * 16) * BN + warpN * 64 + j * 16,
                c[i][j], BN, wmma::mem_row_major);
    __syncthreads();

#pragma unroll
    for (int p = 0; p < 16; p++) {
        int idx = t + p * 256;
        int row = idx >> 5;
        int c4  = idx & 31;
        int node = m0 + row;
        if (node < n_nodes) {
            *reinterpret_cast<float4*>(out + (size_t)node * OUT_F + c4 * 4) =
                *reinterpret_cast<const float4*>(Csm + (size_t)row * BN + c4 * 4);
        }
    }
}

// ---------------------------------------------------------------------------
extern "C" void kernel_launch(void* const* d_in, const int* in_sizes, int n_in,
                              void* d_out, int out_size) {
    const float* h      = (const float*)d_in[0];
    const float* eftr   = (const float*)d_in[1];
    const float* weight = (const float*)d_in[2];
    const float* W_w    = (const float*)d_in[3];
    const float* W_b    = (const float*)d_in[4];
    const float* bias   = (const float*)d_in[5];
    const int*   src    = (const int*)d_in[6];
    const int*   dst    = (const int*)d_in[7];
    float* out = (float*)d_out;

    int n_nodes = in_sizes[0] / IN_F;
    int n_edges = in_sizes[7];
    int nb  = (n_nodes + 255) / 256;           // 196
    int nbh = (n_edges + 255) / 256;           // 3125
    int nhc = (n_nodes * 32 + 255) / 256;      // 6250

    static bool attr_done = false;
    if (!attr_done) {
        cudaFuncSetAttribute(gemm_wmma_kernel,
                             cudaFuncAttributeMaxDynamicSharedMemorySize, SM_TOTAL);
        attr_done = true;
    }

    prep1_kernel<<<FEAT + (n_nodes + 127) / 128, 128>>>(weight, W_w, n_nodes);
    prep_B_kernel<<<KTOT, OUT_F>>>(W_w, W_b, bias);
    hist_hconv_kernel<<<nbh + nhc, 256>>>(dst, h, n_edges, n_nodes, nbh);
    scanA_kernel<<<nb, 256>>>(n_nodes);
    scanB_kernel<<<1, 256>>>(nb, n_nodes);
    scanC_kernel<<<nb, 256>>>(n_nodes);
    bucket_kernel<<<nbh, 256>>>(src, dst, n_edges);
    aggregate_kernel<<<(n_nodes * 32 + 255) / 256, 256>>>(h, eftr, n_nodes);
    gemm_wmma_kernel<<<(n_nodes + BM - 1) / BM, 256, SM_TOTAL>>>(out, n_nodes);
}

// round 11
// speedup vs baseline: 1.3759x; 1.0428x over previous
#include <cuda_runtime.h>
#include <cuda_bf16.h>
#include <mma.h>
#include <cstdint>

using namespace nvcuda;

// ---------------------------------------------------------------------------
// FSRGraphConv round 11: counting-sort aggregation (fused single-launch scan)
// + pre-split bf16 X (hi/lo) + cp.async WMMA bf16 split-precision GEMM
// (2 blocks/SM). out = [h_dst | feat_mean] @ [W1t ; weight@W2^T] + (W_b+bias)
// ---------------------------------------------------------------------------

#define IN_F   128
#define E_F    32
#define FEAT   160
#define OUT_F  128
#define KTOT   288
#define MAX_NODES 50000
#define NPAD   50048          // 391 * 128 (rows >= n_nodes stay zero forever)
#define MAX_EDGES 800000
#define XLD    288

__device__ int  g_cnt[MAX_NODES];
__device__ int  g_off[MAX_NODES + 1];
__device__ int  g_cur[MAX_NODES];
__device__ int  g_bsum[256];
__device__ int  g_sync1;
__device__ int  g_sync2;
__device__ __align__(8) int2 g_pairs[MAX_EDGES];
__device__ __align__(16) float g_Wc[FEAT * OUT_F];
__device__ __align__(16) __nv_bfloat16 g_Xhi[(size_t)NPAD * XLD];
__device__ __align__(16) __nv_bfloat16 g_Xlo[(size_t)NPAD * XLD];
__device__ __align__(16) __nv_bfloat16 g_Bhi[KTOT * OUT_F];
__device__ __align__(16) __nv_bfloat16 g_Blo[KTOT * OUT_F];
__device__ __align__(16) float g_bvt[16 * OUT_F];

// ========================= bf16 split helpers ===============================
__device__ __forceinline__ uint32_t pk_bf2(__nv_bfloat16 a, __nv_bfloat16 b) {
    return (uint32_t)__bfloat16_as_ushort(a) |
           ((uint32_t)__bfloat16_as_ushort(b) << 16);
}
__device__ __forceinline__ void split4(float4 v, uint2& hi, uint2& lo) {
    __nv_bfloat16 h0 = __float2bfloat16(v.x);
    __nv_bfloat16 h1 = __float2bfloat16(v.y);
    __nv_bfloat16 h2 = __float2bfloat16(v.z);
    __nv_bfloat16 h3 = __float2bfloat16(v.w);
    __nv_bfloat16 l0 = __float2bfloat16(v.x - __bfloat162float(h0));
    __nv_bfloat16 l1 = __float2bfloat16(v.y - __bfloat162float(h1));
    __nv_bfloat16 l2 = __float2bfloat16(v.z - __bfloat162float(h2));
    __nv_bfloat16 l3 = __float2bfloat16(v.w - __bfloat162float(h3));
    hi = make_uint2(pk_bf2(h0, h1), pk_bf2(h2, h3));
    lo = make_uint2(pk_bf2(l0, l1), pk_bf2(l2, l3));
}

// ===================== merged prep 1: Wc + zero cnt + sync reset ============
__global__ void prep1_kernel(const float* __restrict__ weight,
                             const float* __restrict__ W_w, int n_nodes) {
    int b = blockIdx.x;
    if (b == 0 && threadIdx.x == 0) { g_sync1 = 0; g_sync2 = 0; }
    if (b < FEAT) {
        __shared__ float wrow[OUT_F];
        int k = b, o = threadIdx.x;
        wrow[o] = weight[k * OUT_F + o];
        __syncthreads();
        const float* wr = W_w + (size_t)o * (IN_F + OUT_F) + IN_F;
        float s = 0.f;
#pragma unroll 4
        for (int c = 0; c < OUT_F; c++) s = fmaf(wrow[c], wr[c], s);
        g_Wc[k * OUT_F + o] = s;
    } else {
        int i = (b - FEAT) * 128 + threadIdx.x;
        if (i < n_nodes) g_cnt[i] = 0;
    }
}

// ===================== prep 2: B hi/lo + bvt =================================
__global__ void prep_B_kernel(const float* __restrict__ W_w,
                              const float* __restrict__ W_b,
                              const float* __restrict__ bias) {
    int k = blockIdx.x;      // 0..287
    int n = threadIdx.x;     // 0..127
    float w = (k < IN_F) ? W_w[(size_t)n * (IN_F + OUT_F) + k]
                         : g_Wc[(size_t)(k - IN_F) * OUT_F + n];
    __nv_bfloat16 hi = __float2bfloat16(w);
    __nv_bfloat16 lo = __float2bfloat16(w - __bfloat162float(hi));
    g_Bhi[(size_t)k * OUT_F + n] = hi;
    g_Blo[(size_t)k * OUT_F + n] = lo;
    if (k < 16) g_bvt[k * OUT_F + n] = W_b[n] + bias[n];
}

// ===================== merged hist + hconv ==================================
__global__ void hist_hconv_kernel(const int* __restrict__ dst_idx,
                                  const float* __restrict__ h,
                                  int n_edges, int n_nodes, int nbh) {
    int b = blockIdx.x;
    if (b < nbh) {
        int i = b * 256 + threadIdx.x;
        if (i < n_edges) atomicAdd(&g_cnt[dst_idx[i]], 1);
    } else {
        int gid  = (b - nbh) * 256 + threadIdx.x;
        int node = gid >> 5;
        int lane = gid & 31;
        if (node < n_nodes) {
            float4 v = __ldg(reinterpret_cast<const float4*>(h + (size_t)node * IN_F) + lane);
            uint2 hi, lo;
            split4(v, hi, lo);
            size_t e = (size_t)node * XLD + lane * 4;
            *reinterpret_cast<uint2*>(g_Xhi + e) = hi;
            *reinterpret_cast<uint2*>(g_Xlo + e) = lo;
        }
    }
}

// ===================== fused single-launch scan ==============================
// 128 persistent blocks x 256 threads (all co-resident: spin-sync is safe).
// Phase1: per-tile local exclusive scan + tile sums. Grid sync. Block 0 scans
// tile sums. Grid sync. Phase2: add tile bases, write g_off/g_cur.
#define SCAN_BLOCKS 128
__global__ void scan_fused_kernel(int n) {
    __shared__ int ss[256];
    int t = threadIdx.x;
    int ntiles = (n + 255) >> 8;

    // phase 1
    for (int tile = blockIdx.x; tile < ntiles; tile += SCAN_BLOCKS) {
        int i = tile * 256 + t;
        int c = (i < n) ? g_cnt[i] : 0;
        ss[t] = c; __syncthreads();
        for (int off = 1; off < 256; off <<= 1) {
            int v = (t >= off) ? ss[t - off] : 0;
            __syncthreads();
            ss[t] += v;
            __syncthreads();
        }
        if (i < n) g_off[i] = ss[t] - c;      // local exclusive (temp)
        if (t == 255) g_bsum[tile] = ss[255];
        __syncthreads();
    }

    // grid barrier 1
    __threadfence();
    if (t == 0) atomicAdd(&g_sync1, 1);
    if (blockIdx.x == 0) {
        if (t == 0) while (atomicAdd(&g_sync1, 0) < SCAN_BLOCKS) __nanosleep(64);
        __syncthreads();
        // scan tile sums (ntiles <= 256)
        int v = (t < ntiles) ? g_bsum[t] : 0;
        ss[t] = v; __syncthreads();
        for (int off = 1; off < 256; off <<= 1) {
            int x = (t >= off) ? ss[t - off] : 0;
            __syncthreads();
            ss[t] += x;
            __syncthreads();
        }
        if (t < ntiles) g_bsum[t] = ss[t] - v;   // exclusive bases
        if (t == 255) g_off[n] = ss[255];
        __threadfence();
        __syncthreads();
        if (t == 0) atomicAdd(&g_sync2, 1);
    } else {
        if (t == 0) while (atomicAdd(&g_sync2, 0) == 0) __nanosleep(64);
        __syncthreads();
    }

    // phase 2
    for (int tile = blockIdx.x; tile < ntiles; tile += SCAN_BLOCKS) {
        int i = tile * 256 + t;
        if (i < n) {
            int o = g_off[i] + g_bsum[tile];
            g_off[i] = o;
            g_cur[i] = o;
        }
    }
}

__global__ void bucket_kernel(const int* __restrict__ src_idx,
                              const int* __restrict__ dst_idx,
                              int n_edges) {
    int e = blockIdx.x * blockDim.x + threadIdx.x;
    if (e < n_edges) {
        int d = dst_idx[e];
        int pos = atomicAdd(&g_cur[d], 1);
        g_pairs[pos] = make_int2(src_idx[e], e);
    }
}

// warp per dst: mean over sorted edges -> Xhi/Xlo[:,128:288]. 4-edge unroll.
__global__ void aggregate_kernel(const float* __restrict__ h,
                                 const float* __restrict__ eftr,
                                 int n_nodes) {
    int lane = threadIdx.x & 31;
    int w    = (blockIdx.x * blockDim.x + threadIdx.x) >> 5;
    if (w >= n_nodes) return;

    int start = g_off[w];
    int end   = g_off[w + 1];
    int n     = end - start;

    float4 a0 = make_float4(0.f,0.f,0.f,0.f), a1 = a0, a2 = a0, a3 = a0;
    float  e0 = 0.f, e1 = 0.f, e2 = 0.f, e3 = 0.f;

    int j = start;
    for (; j + 3 < end; j += 4) {
        int2 c0 = g_pairs[j];
        int2 c1 = g_pairs[j + 1];
        int2 c2 = g_pairs[j + 2];
        int2 c3 = g_pairs[j + 3];
        float4 h0 = __ldg(reinterpret_cast<const float4*>(h + (size_t)c0.x * IN_F) + lane);
        float4 h1 = __ldg(reinterpret_cast<const float4*>(h + (size_t)c1.x * IN_F) + lane);
        float4 h2 = __ldg(reinterpret_cast<const float4*>(h + (size_t)c2.x * IN_F) + lane);
        float4 h3 = __ldg(reinterpret_cast<const float4*>(h + (size_t)c3.x * IN_F) + lane);
        float  v0 = __ldg(eftr + (size_t)c0.y * E_F + lane);
        float  v1 = __ldg(eftr + (size_t)c1.y * E_F + lane);
        float  v2 = __ldg(eftr + (size_t)c2.y * E_F + lane);
        float  v3 = __ldg(eftr + (size_t)c3.y * E_F + lane);
        a0.x += h0.x; a0.y += h0.y; a0.z += h0.z; a0.w += h0.w; e0 += v0;
        a1.x += h1.x; a1.y += h1.y; a1.z += h1.z; a1.w += h1.w; e1 += v1;
        a2.x += h2.x; a2.y += h2.y; a2.z += h2.z; a2.w += h2.w; e2 += v2;
        a3.x += h3.x; a3.y += h3.y; a3.z += h3.z; a3.w += h3.w; e3 += v3;
    }
    for (; j < end; j++) {
        int2 c0 = g_pairs[j];
        float4 h0 = __ldg(reinterpret_cast<const float4*>(h + (size_t)c0.x * IN_F) + lane);
        float  v0 = __ldg(eftr + (size_t)c0.y * E_F + lane);
        a0.x += h0.x; a0.y += h0.y; a0.z += h0.z; a0.w += h0.w; e0 += v0;
    }

    float inv = 1.f / (float)max(n, 1);
    float4 ah = make_float4((a0.x + a1.x + a2.x + a3.x) * inv,
                            (a0.y + a1.y + a2.y + a3.y) * inv,
                            (a0.z + a1.z + a2.z + a3.z) * inv,
                            (a0.w + a1.w + a2.w + a3.w) * inv);
    float  ae = (e0 + e1 + e2 + e3) * inv;

    uint2 hi, lo;
    split4(ah, hi, lo);
    size_t eh = (size_t)w * XLD + IN_F + lane * 4;
    *reinterpret_cast<uint2*>(g_Xhi + eh) = hi;
    *reinterpret_cast<uint2*>(g_Xlo + eh) = lo;

    __nv_bfloat16 ehi = __float2bfloat16(ae);
    __nv_bfloat16 elo = __float2bfloat16(ae - __bfloat162float(ehi));
    size_t ee = (size_t)w * XLD + 256 + lane;
    g_Xhi[ee] = ehi;
    g_Xlo[ee] = elo;
}

// ========================= cp.async WMMA GEMM ===============================
#define BM 128
#define BN 128
#define BK 32
#define NKC 9
#define ALDM 56
#define BLDM 136
#define A_BYTES (BM * ALDM * 2)
#define B_BYTES (BK * BLDM * 2)
#define ST_AHI 0
#define ST_ALO (A_BYTES)
#define ST_BHI (2 * A_BYTES)
#define ST_BLO (2 * A_BYTES + B_BYTES)
#define STAGE_BYTES (2 * A_BYTES + 2 * B_BYTES)   // 46080
#define SM_TOTAL (2 * STAGE_BYTES)                // 92160

__device__ __forceinline__ uint32_t smem_u32(const void* p) {
    return (uint32_t)__cvta_generic_to_shared(p);
}
__device__ __forceinline__ void cp16(uint32_t sdst, const void* gsrc) {
    asm volatile("cp.async.ca.shared.global [%0], [%1], 16;"
                 :: "r"(sdst), "l"(gsrc));
}

__global__ __launch_bounds__(256, 2) void gemm_wmma_kernel(
    float* __restrict__ out, int n_nodes)
{
    extern __shared__ __align__(16) char dsm[];
    float* Csm = reinterpret_cast<float*>(dsm);
    const uint32_t sb = smem_u32(dsm);

    int m0 = blockIdx.x * BM;
    int t  = threadIdx.x;
    int wid = t >> 5;
    int warpM = wid & 3;
    int warpN = wid >> 2;

    int am0 = t >> 2,          aq0 = t & 3;
    int am1 = (t + 256) >> 2,  aq1 = (t + 256) & 3;
    int bk0 = t >> 4,          bq0 = t & 15;
    int bk1 = (t + 256) >> 4,  bq1 = (t + 256) & 15;

    const __nv_bfloat16* gA0h = g_Xhi + (size_t)(m0 + am0) * XLD + aq0 * 8;
    const __nv_bfloat16* gA0l = g_Xlo + (size_t)(m0 + am0) * XLD + aq0 * 8;
    const __nv_bfloat16* gA1h = g_Xhi + (size_t)(m0 + am1) * XLD + aq1 * 8;
    const __nv_bfloat16* gA1l = g_Xlo + (size_t)(m0 + am1) * XLD + aq1 * 8;
    const __nv_bfloat16* gB0h = g_Bhi + (size_t)bk0 * OUT_F + bq0 * 8;
    const __nv_bfloat16* gB0l = g_Blo + (size_t)bk0 * OUT_F + bq0 * 8;
    const __nv_bfloat16* gB1h = g_Bhi + (size_t)bk1 * OUT_F + bq1 * 8;
    const __nv_bfloat16* gB1l = g_Blo + (size_t)bk1 * OUT_F + bq1 * 8;

    uint32_t sA0 = sb + (am0 * ALDM + aq0 * 8) * 2;
    uint32_t sA1 = sb + (am1 * ALDM + aq1 * 8) * 2;
    uint32_t sB0 = sb + ST_BHI + (bk0 * BLDM + bq0 * 8) * 2;
    uint32_t sB1 = sb + ST_BHI + (bk1 * BLDM + bq1 * 8) * 2;

    auto load_stage = [&](int kc, int buf) {
        uint32_t so = buf * STAGE_BYTES;
        int ko = kc * BK;
        cp16(sA0 + so,           gA0h + ko);
        cp16(sA0 + so + A_BYTES, gA0l + ko);
        cp16(sA1 + so,           gA1h + ko);
        cp16(sA1 + so + A_BYTES, gA1l + ko);
        size_t bo = (size_t)ko * OUT_F;
        cp16(sB0 + so,           gB0h + bo);
        cp16(sB0 + so + B_BYTES, gB0l + bo);
        cp16(sB1 + so,           gB1h + bo);
        cp16(sB1 + so + B_BYTES, gB1l + bo);
        asm volatile("cp.async.commit_group;");
    };

    wmma::fragment<wmma::accumulator, 16, 16, 16, float> c[2][4];
#pragma unroll
    for (int i = 0; i < 2; i++)
#pragma unroll
        for (int j = 0; j < 4; j++)
            wmma::load_matrix_sync(c[i][j], g_bvt + warpN * 64 + j * 16,
                                   OUT_F, wmma::mem_row_major);

    load_stage(0, 0);

    for (int kc = 0; kc < NKC; kc++) {
        if (kc + 1 < NKC) {
            load_stage(kc + 1, (kc + 1) & 1);
            asm volatile("cp.async.wait_group 1;");
        } else {
            asm volatile("cp.async.wait_group 0;");
        }
        __syncthreads();

        char* st = dsm + (kc & 1) * STAGE_BYTES;
        __nv_bfloat16* Ahi = reinterpret_cast<__nv_bfloat16*>(st);
        __nv_bfloat16* Alo = reinterpret_cast<__nv_bfloat16*>(st + ST_ALO);
        __nv_bfloat16* Bhi = reinterpret_cast<__nv_bfloat16*>(st + ST_BHI);
        __nv_bfloat16* Blo = reinterpret_cast<__nv_bfloat16*>(st + ST_BLO);

#pragma unroll
        for (int ks = 0; ks < 2; ks++) {
            wmma::fragment<wmma::matrix_a, 16, 16, 16, __nv_bfloat16, wmma::row_major> ah[2], al[2];
#pragma unroll
            for (int i = 0; i < 2; i++) {
                wmma::load_matrix_sync(ah[i], Ahi + (warpM * 32 + i * 16) * ALDM + ks * 16, ALDM);
                wmma::load_matrix_sync(al[i], Alo + (warpM * 32 + i * 16) * ALDM + ks * 16, ALDM);
            }
            // load B fragments inside j-loop to bound live registers (2 blk/SM)
#pragma unroll
            for (int j = 0; j < 4; j++) {
                wmma::fragment<wmma::matrix_b, 16, 16, 16, __nv_bfloat16, wmma::row_major> wh, wl;
                wmma::load_matrix_sync(wh, Bhi + (ks * 16) * BLDM + warpN * 64 + j * 16, BLDM);
                wmma::load_matrix_sync(wl, Blo + (ks * 16) * BLDM + warpN * 64 + j * 16, BLDM);
#pragma unroll
                for (int i = 0; i < 2; i++) {
                    wmma::mma_sync(c[i][j], ah[i], wh, c[i][j]);
                    wmma::mma_sync(c[i][j], ah[i], wl, c[i][j]);
                    wmma::mma_sync(c[i][j], al[i], wh, c[i][j]);
                }
            }
        }
        __syncthreads();
    }

    // epilogue via smem staging
#pragma unroll
    for (int i = 0; i < 2; i++)
#pragma unroll
        for (int j = 0; j < 4; j++)
            wmma::store_matrix_sync(
                Csm + (size_t)(warpM * 32 + i * 16) * BN + warpN * 64 + j * 16,
                c[i][j], BN, wmma::mem_row_major);
    __syncthreads();

#pragma unroll
    for (int p = 0; p < 16; p++) {
        int idx = t + p * 256;
        int row = idx >> 5;
        int c4  = idx & 31;
        int node = m0 + row;
        if (node < n_nodes) {
            *reinterpret_cast<float4*>(out + (size_t)node * OUT_F + c4 * 4) =
                *reinterpret_cast<const float4*>(Csm + (size_t)row * BN + c4 * 4);
        }
    }
}

// ---------------------------------------------------------------------------
extern "C" void kernel_launch(void* const* d_in, const int* in_sizes, int n_in,
                              void* d_out, int out_size) {
    const float* h      = (const float*)d_in[0];
    const float* eftr   = (const float*)d_in[1];
    const float* weight = (const float*)d_in[2];
    const float* W_w    = (const float*)d_in[3];
    const float* W_b    = (const float*)d_in[4];
    const float* bias   = (const float*)d_in[5];
    const int*   src    = (const int*)d_in[6];
    const int*   dst    = (const int*)d_in[7];
    float* out = (float*)d_out;

    int n_nodes = in_sizes[0] / IN_F;
    int n_edges = in_sizes[7];
    int nbh = (n_edges + 255) / 256;           // 3125
    int nhc = (n_nodes * 32 + 255) / 256;      // 6250

    static bool attr_done = false;
    if (!attr_done) {
        cudaFuncSetAttribute(gemm_wmma_kernel,
                             cudaFuncAttributeMaxDynamicSharedMemorySize, SM_TOTAL);
        attr_done = true;
    }

    prep1_kernel<<<FEAT + (n_nodes + 127) / 128, 128>>>(weight, W_w, n_nodes);
    prep_B_kernel<<<KTOT, OUT_F>>>(W_w, W_b, bias);
    hist_hconv_kernel<<<nbh + nhc, 256>>>(dst, h, n_edges, n_nodes, nbh);
    scan_fused_kernel<<<SCAN_BLOCKS, 256>>>(n_nodes);
    bucket_kernel<<<nbh, 256>>>(src, dst, n_edges);
    aggregate_kernel<<<(n_nodes * 32 + 255) / 256, 256>>>(h, eftr, n_nodes);
    gemm_wmma_kernel<<<(n_nodes + BM - 1) / BM, 256, SM_TOTAL>>>(out, n_nodes);
}

// round 12
// speedup vs baseline: 1.4453x; 1.0505x over previous
#include <cuda_runtime.h>
#include <cuda_bf16.h>
#include <mma.h>
#include <cstdint>

using namespace nvcuda;

// ---------------------------------------------------------------------------
// FSRGraphConv round 12: two-stream overlap inside graph capture.
//   stream 1 (capture): zero -> hist -> scan -> bucket -> aggregate -> gemm
//   stream 2:           prep_Wc -> prep_B -> hconv  (joins before gemm)
// Kernels identical to R11 (aggregate 4-unroll, fused scan, cp.async WMMA).
// ---------------------------------------------------------------------------

#define IN_F   128
#define E_F    32
#define FEAT   160
#define OUT_F  128
#define KTOT   288
#define MAX_NODES 50000
#define NPAD   50048
#define MAX_EDGES 800000
#define XLD    288

__device__ int  g_cnt[MAX_NODES];
__device__ int  g_off[MAX_NODES + 1];
__device__ int  g_cur[MAX_NODES];
__device__ int  g_bsum[256];
__device__ int  g_sync1;
__device__ int  g_sync2;
__device__ __align__(8) int2 g_pairs[MAX_EDGES];
__device__ __align__(16) float g_Wc[FEAT * OUT_F];
__device__ __align__(16) __nv_bfloat16 g_Xhi[(size_t)NPAD * XLD];
__device__ __align__(16) __nv_bfloat16 g_Xlo[(size_t)NPAD * XLD];
__device__ __align__(16) __nv_bfloat16 g_Bhi[KTOT * OUT_F];
__device__ __align__(16) __nv_bfloat16 g_Blo[KTOT * OUT_F];
__device__ __align__(16) float g_bvt[16 * OUT_F];

// ========================= bf16 split helpers ===============================
__device__ __forceinline__ uint32_t pk_bf2(__nv_bfloat16 a, __nv_bfloat16 b) {
    return (uint32_t)__bfloat16_as_ushort(a) |
           ((uint32_t)__bfloat16_as_ushort(b) << 16);
}
__device__ __forceinline__ void split4(float4 v, uint2& hi, uint2& lo) {
    __nv_bfloat16 h0 = __float2bfloat16(v.x);
    __nv_bfloat16 h1 = __float2bfloat16(v.y);
    __nv_bfloat16 h2 = __float2bfloat16(v.z);
    __nv_bfloat16 h3 = __float2bfloat16(v.w);
    __nv_bfloat16 l0 = __float2bfloat16(v.x - __bfloat162float(h0));
    __nv_bfloat16 l1 = __float2bfloat16(v.y - __bfloat162float(h1));
    __nv_bfloat16 l2 = __float2bfloat16(v.z - __bfloat162float(h2));
    __nv_bfloat16 l3 = __float2bfloat16(v.w - __bfloat162float(h3));
    hi = make_uint2(pk_bf2(h0, h1), pk_bf2(h2, h3));
    lo = make_uint2(pk_bf2(l0, l1), pk_bf2(l2, l3));
}

// ===================== stream 1: zero cnt + sync flags ======================
__global__ void zero_kernel(int n_nodes) {
    if (blockIdx.x == 0 && threadIdx.x == 0) { g_sync1 = 0; g_sync2 = 0; }
    int i = blockIdx.x * 256 + threadIdx.x;
    if (i < n_nodes) g_cnt[i] = 0;
}

// ===================== stream 2: weight prep ================================
__global__ void prep_wc_kernel(const float* __restrict__ weight,
                               const float* __restrict__ W_w) {
    __shared__ float wrow[OUT_F];
    int k = blockIdx.x, o = threadIdx.x;
    wrow[o] = weight[k * OUT_F + o];
    __syncthreads();
    const float* wr = W_w + (size_t)o * (IN_F + OUT_F) + IN_F;
    float s = 0.f;
#pragma unroll 4
    for (int c = 0; c < OUT_F; c++) s = fmaf(wrow[c], wr[c], s);
    g_Wc[k * OUT_F + o] = s;
}

__global__ void prep_B_kernel(const float* __restrict__ W_w,
                              const float* __restrict__ W_b,
                              const float* __restrict__ bias) {
    int k = blockIdx.x;      // 0..287
    int n = threadIdx.x;     // 0..127
    float w = (k < IN_F) ? W_w[(size_t)n * (IN_F + OUT_F) + k]
                         : g_Wc[(size_t)(k - IN_F) * OUT_F + n];
    __nv_bfloat16 hi = __float2bfloat16(w);
    __nv_bfloat16 lo = __float2bfloat16(w - __bfloat162float(hi));
    g_Bhi[(size_t)k * OUT_F + n] = hi;
    g_Blo[(size_t)k * OUT_F + n] = lo;
    if (k < 16) g_bvt[k * OUT_F + n] = W_b[n] + bias[n];
}

__global__ void hconv_kernel(const float* __restrict__ h, int n_nodes) {
    int gid  = blockIdx.x * 256 + threadIdx.x;
    int node = gid >> 5;
    int lane = gid & 31;
    if (node >= n_nodes) return;
    float4 v = __ldg(reinterpret_cast<const float4*>(h + (size_t)node * IN_F) + lane);
    uint2 hi, lo;
    split4(v, hi, lo);
    size_t e = (size_t)node * XLD + lane * 4;
    *reinterpret_cast<uint2*>(g_Xhi + e) = hi;
    *reinterpret_cast<uint2*>(g_Xlo + e) = lo;
}

// ===================== stream 1: hist / scan / bucket / aggregate ===========
__global__ void hist_kernel(const int* __restrict__ dst_idx, int n_edges) {
    int i = blockIdx.x * 256 + threadIdx.x;
    if (i < n_edges) atomicAdd(&g_cnt[dst_idx[i]], 1);
}

#define SCAN_BLOCKS 128
__global__ void scan_fused_kernel(int n) {
    __shared__ int ss[256];
    int t = threadIdx.x;
    int ntiles = (n + 255) >> 8;

    for (int tile = blockIdx.x; tile < ntiles; tile += SCAN_BLOCKS) {
        int i = tile * 256 + t;
        int c = (i < n) ? g_cnt[i] : 0;
        ss[t] = c; __syncthreads();
        for (int off = 1; off < 256; off <<= 1) {
            int v = (t >= off) ? ss[t - off] : 0;
            __syncthreads();
            ss[t] += v;
            __syncthreads();
        }
        if (i < n) g_off[i] = ss[t] - c;
        if (t == 255) g_bsum[tile] = ss[255];
        __syncthreads();
    }

    __threadfence();
    if (t == 0) atomicAdd(&g_sync1, 1);
    if (blockIdx.x == 0) {
        if (t == 0) while (atomicAdd(&g_sync1, 0) < SCAN_BLOCKS) __nanosleep(64);
        __syncthreads();
        int v = (t < ntiles) ? g_bsum[t] : 0;
        ss[t] = v; __syncthreads();
        for (int off = 1; off < 256; off <<= 1) {
            int x = (t >= off) ? ss[t - off] : 0;
            __syncthreads();
            ss[t] += x;
            __syncthreads();
        }
        if (t < ntiles) g_bsum[t] = ss[t] - v;
        if (t == 255) g_off[n] = ss[255];
        __threadfence();
        __syncthreads();
        if (t == 0) atomicAdd(&g_sync2, 1);
    } else {
        if (t == 0) while (atomicAdd(&g_sync2, 0) == 0) __nanosleep(64);
        __syncthreads();
    }

    for (int tile = blockIdx.x; tile < ntiles; tile += SCAN_BLOCKS) {
        int i = tile * 256 + t;
        if (i < n) {
            int o = g_off[i] + g_bsum[tile];
            g_off[i] = o;
            g_cur[i] = o;
        }
    }
}

__global__ void bucket_kernel(const int* __restrict__ src_idx,
                              const int* __restrict__ dst_idx,
                              int n_edges) {
    int e = blockIdx.x * blockDim.x + threadIdx.x;
    if (e < n_edges) {
        int d = dst_idx[e];
        int pos = atomicAdd(&g_cur[d], 1);
        g_pairs[pos] = make_int2(src_idx[e], e);
    }
}

__global__ void aggregate_kernel(const float* __restrict__ h,
                                 const float* __restrict__ eftr,
                                 int n_nodes) {
    int lane = threadIdx.x & 31;
    int w    = (blockIdx.x * blockDim.x + threadIdx.x) >> 5;
    if (w >= n_nodes) return;

    int start = g_off[w];
    int end   = g_off[w + 1];
    int n     = end - start;

    float4 a0 = make_float4(0.f,0.f,0.f,0.f), a1 = a0, a2 = a0, a3 = a0;
    float  e0 = 0.f, e1 = 0.f, e2 = 0.f, e3 = 0.f;

    int j = start;
    for (; j + 3 < end; j += 4) {
        int2 c0 = g_pairs[j];
        int2 c1 = g_pairs[j + 1];
        int2 c2 = g_pairs[j + 2];
        int2 c3 = g_pairs[j + 3];
        float4 h0 = __ldg(reinterpret_cast<const float4*>(h + (size_t)c0.x * IN_F) + lane);
        float4 h1 = __ldg(reinterpret_cast<const float4*>(h + (size_t)c1.x * IN_F) + lane);
        float4 h2 = __ldg(reinterpret_cast<const float4*>(h + (size_t)c2.x * IN_F) + lane);
        float4 h3 = __ldg(reinterpret_cast<const float4*>(h + (size_t)c3.x * IN_F) + lane);
        float  v0 = __ldg(eftr + (size_t)c0.y * E_F + lane);
        float  v1 = __ldg(eftr + (size_t)c1.y * E_F + lane);
        float  v2 = __ldg(eftr + (size_t)c2.y * E_F + lane);
        float  v3 = __ldg(eftr + (size_t)c3.y * E_F + lane);
        a0.x += h0.x; a0.y += h0.y; a0.z += h0.z; a0.w += h0.w; e0 += v0;
        a1.x += h1.x; a1.y += h1.y; a1.z += h1.z; a1.w += h1.w; e1 += v1;
        a2.x += h2.x; a2.y += h2.y; a2.z += h2.z; a2.w += h2.w; e2 += v2;
        a3.x += h3.x; a3.y += h3.y; a3.z += h3.z; a3.w += h3.w; e3 += v3;
    }
    for (; j < end; j++) {
        int2 c0 = g_pairs[j];
        float4 h0 = __ldg(reinterpret_cast<const float4*>(h + (size_t)c0.x * IN_F) + lane);
        float  v0 = __ldg(eftr + (size_t)c0.y * E_F + lane);
        a0.x += h0.x; a0.y += h0.y; a0.z += h0.z; a0.w += h0.w; e0 += v0;
    }

    float inv = 1.f / (float)max(n, 1);
    float4 ah = make_float4((a0.x + a1.x + a2.x + a3.x) * inv,
                            (a0.y + a1.y + a2.y + a3.y) * inv,
                            (a0.z + a1.z + a2.z + a3.z) * inv,
                            (a0.w + a1.w + a2.w + a3.w) * inv);
    float  ae = (e0 + e1 + e2 + e3) * inv;

    uint2 hi, lo;
    split4(ah, hi, lo);
    size_t eh = (size_t)w * XLD + IN_F + lane * 4;
    *reinterpret_cast<uint2*>(g_Xhi + eh) = hi;
    *reinterpret_cast<uint2*>(g_Xlo + eh) = lo;

    __nv_bfloat16 ehi = __float2bfloat16(ae);
    __nv_bfloat16 elo = __float2bfloat16(ae - __bfloat162float(ehi));
    size_t ee = (size_t)w * XLD + 256 + lane;
    g_Xhi[ee] = ehi;
    g_Xlo[ee] = elo;
}

// ========================= cp.async WMMA GEMM ===============================
#define BM 128
#define BN 128
#define BK 32
#define NKC 9
#define ALDM 56
#define BLDM 136
#define A_BYTES (BM * ALDM * 2)
#define B_BYTES (BK * BLDM * 2)
#define ST_AHI 0
#define ST_ALO (A_BYTES)
#define ST_BHI (2 * A_BYTES)
#define ST_BLO (2 * A_BYTES + B_BYTES)
#define STAGE_BYTES (2 * A_BYTES + 2 * B_BYTES)   // 46080
#define SM_TOTAL (2 * STAGE_BYTES)                // 92160

__device__ __forceinline__ uint32_t smem_u32(const void* p) {
    return (uint32_t)__cvta_generic_to_shared(p);
}
__device__ __forceinline__ void cp16(uint32_t sdst, const void* gsrc) {
    asm volatile("cp.async.ca.shared.global [%0], [%1], 16;"
                 :: "r"(sdst), "l"(gsrc));
}

__global__ __launch_bounds__(256, 2) void gemm_wmma_kernel(
    float* __restrict__ out, int n_nodes)
{
    extern __shared__ __align__(16) char dsm[];
    float* Csm = reinterpret_cast<float*>(dsm);
    const uint32_t sb = smem_u32(dsm);

    int m0 = blockIdx.x * BM;
    int t  = threadIdx.x;
    int wid = t >> 5;
    int warpM = wid & 3;
    int warpN = wid >> 2;

    int am0 = t >> 2,          aq0 = t & 3;
    int am1 = (t + 256) >> 2,  aq1 = (t + 256) & 3;
    int bk0 = t >> 4,          bq0 = t & 15;
    int bk1 = (t + 256) >> 4,  bq1 = (t + 256) & 15;

    const __nv_bfloat16* gA0h = g_Xhi + (size_t)(m0 + am0) * XLD + aq0 * 8;
    const __nv_bfloat16* gA0l = g_Xlo + (size_t)(m0 + am0) * XLD + aq0 * 8;
    const __nv_bfloat16* gA1h = g_Xhi + (size_t)(m0 + am1) * XLD + aq1 * 8;
    const __nv_bfloat16* gA1l = g_Xlo + (size_t)(m0 + am1) * XLD + aq1 * 8;
    const __nv_bfloat16* gB0h = g_Bhi + (size_t)bk0 * OUT_F + bq0 * 8;
    const __nv_bfloat16* gB0l = g_Blo + (size_t)bk0 * OUT_F + bq0 * 8;
    const __nv_bfloat16* gB1h = g_Bhi + (size_t)bk1 * OUT_F + bq1 * 8;
    const __nv_bfloat16* gB1l = g_Blo + (size_t)bk1 * OUT_F + bq1 * 8;

    uint32_t sA0 = sb + (am0 * ALDM + aq0 * 8) * 2;
    uint32_t sA1 = sb + (am1 * ALDM + aq1 * 8) * 2;
    uint32_t sB0 = sb + ST_BHI + (bk0 * BLDM + bq0 * 8) * 2;
    uint32_t sB1 = sb + ST_BHI + (bk1 * BLDM + bq1 * 8) * 2;

    auto load_stage = [&](int kc, int buf) {
        uint32_t so = buf * STAGE_BYTES;
        int ko = kc * BK;
        cp16(sA0 + so,           gA0h + ko);
        cp16(sA0 + so + A_BYTES, gA0l + ko);
        cp16(sA1 + so,           gA1h + ko);
        cp16(sA1 + so + A_BYTES, gA1l + ko);
        size_t bo = (size_t)ko * OUT_F;
        cp16(sB0 + so,           gB0h + bo);
        cp16(sB0 + so + B_BYTES, gB0l + bo);
        cp16(sB1 + so,           gB1h + bo);
        cp16(sB1 + so + B_BYTES, gB1l + bo);
        asm volatile("cp.async.commit_group;");
    };

    wmma::fragment<wmma::accumulator, 16, 16, 16, float> c[2][4];
#pragma unroll
    for (int i = 0; i < 2; i++)
#pragma unroll
        for (int j = 0; j < 4; j++)
            wmma::load_matrix_sync(c[i][j], g_bvt + warpN * 64 + j * 16,
                                   OUT_F, wmma::mem_row_major);

    load_stage(0, 0);

    for (int kc = 0; kc < NKC; kc++) {
        if (kc + 1 < NKC) {
            load_stage(kc + 1, (kc + 1) & 1);
            asm volatile("cp.async.wait_group 1;");
        } else {
            asm volatile("cp.async.wait_group 0;");
        }
        __syncthreads();

        char* st = dsm + (kc & 1) * STAGE_BYTES;
        __nv_bfloat16* Ahi = reinterpret_cast<__nv_bfloat16*>(st);
        __nv_bfloat16* Alo = reinterpret_cast<__nv_bfloat16*>(st + ST_ALO);
        __nv_bfloat16* Bhi = reinterpret_cast<__nv_bfloat16*>(st + ST_BHI);
        __nv_bfloat16* Blo = reinterpret_cast<__nv_bfloat16*>(st + ST_BLO);

#pragma unroll
        for (int ks = 0; ks < 2; ks++) {
            wmma::fragment<wmma::matrix_a, 16, 16, 16, __nv_bfloat16, wmma::row_major> ah[2], al[2];
#pragma unroll
            for (int i = 0; i < 2; i++) {
                wmma::load_matrix_sync(ah[i], Ahi + (warpM * 32 + i * 16) * ALDM + ks * 16, ALDM);
                wmma::load_matrix_sync(al[i], Alo + (warpM * 32 + i * 16) * ALDM + ks * 16, ALDM);
            }
#pragma unroll
            for (int j = 0; j < 4; j++) {
                wmma::fragment<wmma::matrix_b, 16, 16, 16, __nv_bfloat16, wmma::row_major> wh, wl;
                wmma::load_matrix_sync(wh, Bhi + (ks * 16) * BLDM + warpN * 64 + j * 16, BLDM);
                wmma::load_matrix_sync(wl, Blo + (ks * 16) * BLDM + warpN * 64 + j * 16, BLDM);
#pragma unroll
                for (int i = 0; i < 2; i++) {
                    wmma::mma_sync(c[i][j], ah[i], wh, c[i][j]);
                    wmma::mma_sync(c[i][j], ah[i], wl, c[i][j]);
                    wmma::mma_sync(c[i][j], al[i], wh, c[i][j]);
                }
            }
        }
        __syncthreads();
    }

#pragma unroll
    for (int i = 0; i < 2; i++)
#pragma unroll
        for (int j = 0; j < 4; j++)
            wmma::store_matrix_sync(
                Csm + (size_t)(warpM * 32 + i * 16) * BN + warpN * 64 + j * 16,
                c[i][j], BN, wmma::mem_row_major);
    __syncthreads();

#pragma unroll
    for (int p = 0; p < 16; p++) {
        int idx = t + p * 256;
        int row = idx >> 5;
        int c4  = idx & 31;
        int node = m0 + row;
        if (node < n_nodes) {
            *reinterpret_cast<float4*>(out + (size_t)node * OUT_F + c4 * 4) =
                *reinterpret_cast<const float4*>(Csm + (size_t)row * BN + c4 * 4);
        }
    }
}

// ---------------------------------------------------------------------------
extern "C" void kernel_launch(void* const* d_in, const int* in_sizes, int n_in,
                              void* d_out, int out_size) {
    const float* h      = (const float*)d_in[0];
    const float* eftr   = (const float*)d_in[1];
    const float* weight = (const float*)d_in[2];
    const float* W_w    = (const float*)d_in[3];
    const float* W_b    = (const float*)d_in[4];
    const float* bias   = (const float*)d_in[5];
    const int*   src    = (const int*)d_in[6];
    const int*   dst    = (const int*)d_in[7];
    float* out = (float*)d_out;

    int n_nodes = in_sizes[0] / IN_F;
    int n_edges = in_sizes[7];
    int nb  = (n_nodes + 255) / 256;           // 196
    int nbh = (n_edges + 255) / 256;           // 3125
    int nhc = (n_nodes * 32 + 255) / 256;      // 6250

    static cudaStream_t s2;
    static cudaEvent_t evFork, evJoin;
    static bool init_done = false;
    if (!init_done) {
        cudaFuncSetAttribute(gemm_wmma_kernel,
                             cudaFuncAttributeMaxDynamicSharedMemorySize, SM_TOTAL);
        cudaStreamCreateWithFlags(&s2, cudaStreamNonBlocking);
        cudaEventCreateWithFlags(&evFork, cudaEventDisableTiming);
        cudaEventCreateWithFlags(&evJoin, cudaEventDisableTiming);
        init_done = true;
    }

    // fork side stream off the capture (default) stream
    cudaEventRecord(evFork, 0);
    cudaStreamWaitEvent(s2, evFork, 0);

    // stream 2: weight prep + h conversion (independent of edge pipeline)
    prep_wc_kernel<<<FEAT, OUT_F, 0, s2>>>(weight, W_w);
    prep_B_kernel<<<KTOT, OUT_F, 0, s2>>>(W_w, W_b, bias);
    hconv_kernel<<<nhc, 256, 0, s2>>>(h, n_nodes);
    cudaEventRecord(evJoin, s2);

    // stream 1 (capture stream): edge pipeline
    zero_kernel<<<nb, 256>>>(n_nodes);
    hist_kernel<<<nbh, 256>>>(dst, n_edges);
    scan_fused_kernel<<<SCAN_BLOCKS, 256>>>(n_nodes);
    bucket_kernel<<<nbh, 256>>>(src, dst, n_edges);
    aggregate_kernel<<<(n_nodes * 32 + 255) / 256, 256>>>(h, eftr, n_nodes);

    // join: gemm needs both pipelines
    cudaStreamWaitEvent(0, evJoin, 0);
    gemm_wmma_kernel<<<(n_nodes + BM - 1) / BM, 256, SM_TOTAL>>>(out, n_nodes);
}